// round 12
// baseline (speedup 1.0000x reference)
#include <cuda_runtime.h>
#include <cuda_fp16.h>
#include <cstdint>

namespace {
constexpr int Bc  = 32;
constexpr int Lc  = 4096;
constexpr int Cc  = 512;
constexpr int Hc  = 8;
constexpr int Sc  = 8;
constexpr int NWc = Lc / Sc;
constexpr int Mc  = Bc * Lc;           // 131072
constexpr int NQKV = 3 * Cc;           // 1536

// int8 hi/lo quantization: value = s * (hi*128 + lo), v in [-16200, 16200]
constexpr float XMAX = 6.5f,  WMAX = 0.11f;
constexpr float SA = XMAX / 16200.f, SW = WMAX / 16200.f;
constexpr float INV_SA = 16200.f / XMAX, INV_SW = 16200.f / WMAX;
constexpr float SCALE_HH = SA * SW * 16384.f;
constexpr float SCALE_X  = SA * SW * 128.f;
}

// ---------------- scratch (__device__ globals; no allocations) -------------
__device__ signed char g_x8h[(size_t)Mc * Cc];
__device__ signed char g_x8l[(size_t)Mc * Cc];
__device__ signed char g_w8h[(size_t)NQKV * Cc];    // Wq|Wk|Wv transposed [n][k]
__device__ signed char g_w8l[(size_t)NQKV * Cc];
__device__ __half g_qkv [(size_t)Mc * NQKV];        // fused q|k|v, fp16
__device__ __half g_att [(size_t)Mc * Cc];          // attention out, fp16
__device__ __half g_wpt [(size_t)Cc * Cc];          // Wp transposed fp16
__device__ float  g_bqkv[NQKV];

// ---------------- helpers ---------------------------------------------------
__device__ __forceinline__ uint32_t smem_u32(const void* p) {
    uint32_t a;
    asm("{ .reg .u64 t; cvta.to.shared.u64 t, %1; cvt.u32.u64 %0, t; }" : "=r"(a) : "l"(p));
    return a;
}
#define SW128(off) ((off) ^ (((off) >> 3) & 0x70))

__device__ __forceinline__ void cpa16(uint32_t saddr, const void* g) {
    asm volatile("cp.async.cg.shared.global [%0], [%1], 16;" :: "r"(saddr), "l"(g) : "memory");
}
#define CPA_COMMIT() asm volatile("cp.async.commit_group;" ::: "memory")

__device__ __forceinline__ void ldsm_x4(uint32_t& r0, uint32_t& r1, uint32_t& r2, uint32_t& r3,
                                        uint32_t addr) {
    asm volatile("ldmatrix.sync.aligned.m8n8.x4.shared.b16 {%0,%1,%2,%3}, [%4];"
                 : "=r"(r0), "=r"(r1), "=r"(r2), "=r"(r3) : "r"(addr));
}
__device__ __forceinline__ void mma_fp16(float c[4], const uint32_t a[4], const uint32_t b[2]) {
    asm volatile(
        "mma.sync.aligned.m16n8k16.row.col.f32.f16.f16.f32 "
        "{%0,%1,%2,%3},{%4,%5,%6,%7},{%8,%9},{%0,%1,%2,%3};\n"
        : "+f"(c[0]), "+f"(c[1]), "+f"(c[2]), "+f"(c[3])
        : "r"(a[0]), "r"(a[1]), "r"(a[2]), "r"(a[3]), "r"(b[0]), "r"(b[1]));
}
// int8 MMA m16n8k32, s32 accumulate (exact)
__device__ __forceinline__ void mma_s8(int c[4], const uint32_t a[4], const uint32_t b[2]) {
    asm volatile(
        "mma.sync.aligned.m16n8k32.row.col.s32.s8.s8.s32 "
        "{%0,%1,%2,%3},{%4,%5,%6,%7},{%8,%9},{%0,%1,%2,%3};\n"
        : "+r"(c[0]), "+r"(c[1]), "+r"(c[2]), "+r"(c[3])
        : "r"(a[0]), "r"(a[1]), "r"(a[2]), "r"(a[3]), "r"(b[0]), "r"(b[1]));
}

__device__ __forceinline__ void quant_split(float v, float inv_s, int& hi, int& lo) {
    int q = __float2int_rn(v * inv_s);
    q = max(min(q, 16200), -16200);
    hi = (q + 64) >> 7;           // [-127, 127]
    lo = q - (hi << 7);           // [-64, 63]
}

// ---------------- prep kernels ----------------------------------------------
struct WArgs {
    const float* src[4];          // Wq, Wk, Wv, Wp
    signed char* w8h;
    signed char* w8l;
    __half* wpt;
};

// z in {0,1,2}: transpose + int8 hi/lo quantize into rows z*512...; z==3: Wp -> fp16.
__global__ __launch_bounds__(256) void prep_w_mixed(WArgs args)
{
    __shared__ float t[32][33];
    const int z = blockIdx.z;
    const float* W = args.src[z];
    const int tx = threadIdx.x & 31, ty = threadIdx.x >> 5;
    const int bn = blockIdx.x * 32, bk = blockIdx.y * 32;
    #pragma unroll
    for (int i = 0; i < 32; i += 8)
        t[ty + i][tx] = W[(size_t)(bk + ty + i) * Cc + bn + tx];
    __syncthreads();
    if (z < 3) {
        #pragma unroll
        for (int i = 0; i < 32; i += 8) {
            const float w = t[tx][ty + i];
            int hi, lo;
            quant_split(w, INV_SW, hi, lo);
            const size_t dst = (size_t)(z * Cc + bn + ty + i) * Cc + bk + tx;
            args.w8h[dst] = (signed char)hi;
            args.w8l[dst] = (signed char)lo;
        }
    } else {
        #pragma unroll
        for (int i = 0; i < 32; i += 8)
            args.wpt[(size_t)(bn + ty + i) * Cc + bk + tx] = __float2half(t[tx][ty + i]);
    }
}

__global__ void concat_bias(const float* __restrict__ b0, const float* __restrict__ b1,
                            const float* __restrict__ b2, float* __restrict__ dst)
{
    const int i = blockIdx.x * 256 + threadIdx.x;
    if (i < NQKV) {
        const float* s = (i < Cc) ? b0 : (i < 2 * Cc) ? b1 : b2;
        dst[i] = s[i & (Cc - 1)];
    }
}

// x rolled left by S/2 -> int8 hi/lo planes
__global__ __launch_bounds__(256) void quant_x(
    const float* __restrict__ x, signed char* __restrict__ xh, signed char* __restrict__ xl)
{
    const size_t idx = (size_t)blockIdx.x * 256 + threadIdx.x;  // 8-elt chunk id
    const int row = (int)(idx >> 6);
    const int c8  = (int)(idx & 63) * 8;
    const int pos = row & (Lc - 1);
    const size_t srow = (size_t)(row & ~(Lc - 1)) + ((pos + Sc / 2) & (Lc - 1));
    const float4* src = reinterpret_cast<const float4*>(x + srow * Cc + c8);
    const float4 v0 = src[0], v1 = src[1];
    const float vv[8] = {v0.x, v0.y, v0.z, v0.w, v1.x, v1.y, v1.z, v1.w};
    uint64_t hv = 0, lv = 0;
    #pragma unroll
    for (int i = 0; i < 8; ++i) {
        int hi, lo;
        quant_split(vv[i], INV_SA, hi, lo);
        hv |= (uint64_t)(uint8_t)(signed char)hi << (8 * i);
        lv |= (uint64_t)(uint8_t)(signed char)lo << (8 * i);
    }
    *reinterpret_cast<uint64_t*>(xh + idx * 8) = hv;
    *reinterpret_cast<uint64_t*>(xl + idx * 8) = lv;
}

// ---------------- int8 QKV GEMM ---------------------------------------------
// qkv[M,1536] (fp16) = dequant( x8 @ w8^T ) + bias.
// CTA 128x128xK128(s8), 512 threads, 16 warps (4M x 4N), warp tile 32x32.
// 3 IMMA per k32 (hh -> acc_hh, ah*bl + al*bh -> acc_x), exact s32 accumulate.
namespace gs {
constexpr int BM = 128, BN = 128, BK = 128;     // BK in s8 elements = 128 bytes
constexpr int PLANE  = BM * BK;                 // 16 KB
constexpr int A_HI = 0, A_LO = PLANE, B_HI = 2 * PLANE, B_LO = 3 * PLANE;
constexpr int STAGE  = 4 * PLANE;               // 64 KB
constexpr int NSTAGE = 2;
constexpr int KSTEPS = Cc / BK;                 // 4
constexpr int DYN_SMEM = NSTAGE * STAGE;        // 128 KB
}

__global__ __launch_bounds__(512, 1) void gemm_s8qkv(
    const signed char* __restrict__ Ah, const signed char* __restrict__ Al,
    const signed char* __restrict__ Bh, const signed char* __restrict__ Bl,
    const float* __restrict__ bias, __half* __restrict__ Out)
{
    using namespace gs;
    extern __shared__ char smem[];
    const uint32_t sbase = smem_u32(smem);

    const int tid  = threadIdx.x;
    const int lane = tid & 31;
    const int warp = tid >> 5;       // 0..15
    const int wm   = warp & 3;       // 4 warps along M (32 rows each)
    const int wn   = warp >> 2;      // 4 warps along N (32 cols each)
    const int grp  = lane >> 2;
    const int tig  = lane & 3;
    const int n0   = blockIdx.x * BN;           // N fastest -> L2-friendly
    const int m0   = blockIdx.y * BM;

    // cp.async: 512 threads, per plane each thread loads 2x16B of one row
    const int ld_row = tid >> 2;               // 0..127
    const int ld_c0  = (tid & 3) * 2;          // 16B-chunk pairs
    const signed char* gAh = Ah + (size_t)(m0 + ld_row) * Cc + ld_c0 * 16;
    const signed char* gAl = Al + (size_t)(m0 + ld_row) * Cc + ld_c0 * 16;
    const signed char* gBh = Bh + (size_t)(n0 + ld_row) * Cc + ld_c0 * 16;
    const signed char* gBl = Bl + (size_t)(n0 + ld_row) * Cc + ld_c0 * 16;

    auto load_stage = [&](int slot, int ks) {
        const uint32_t sb = sbase + slot * STAGE;
        const size_t koff = (size_t)ks * BK;
        #pragma unroll
        for (int i = 0; i < 2; ++i) {
            const uint32_t off = SW128(ld_row * 128 + (ld_c0 + i) * 16);
            cpa16(sb + A_HI + off, gAh + koff + i * 16);
            cpa16(sb + A_LO + off, gAl + koff + i * 16);
            cpa16(sb + B_HI + off, gBh + koff + i * 16);
            cpa16(sb + B_LO + off, gBl + koff + i * 16);
        }
    };

    // ldmatrix address components (b16 view over s8 data, 128B rows)
    const uint32_t a_row = (uint32_t)(wm * 32 + (lane & 15)) * 128;
    const uint32_t a_kb  = (uint32_t)(lane >> 4) * 16;
    const uint32_t b_row = (uint32_t)(wn * 32 + (lane & 7) + ((lane >> 4) << 3)) * 128;
    const uint32_t b_kb  = (uint32_t)((lane >> 3) & 1) * 16;

    int acc_hh[2][4][4], acc_x[2][4][4];
    #pragma unroll
    for (int mf = 0; mf < 2; ++mf)
        #pragma unroll
        for (int nf = 0; nf < 4; ++nf)
            #pragma unroll
            for (int t = 0; t < 4; ++t) { acc_hh[mf][nf][t] = 0; acc_x[mf][nf][t] = 0; }

    load_stage(0, 0); CPA_COMMIT();
    load_stage(1, 1); CPA_COMMIT();

    for (int ks = 0; ks < KSTEPS; ++ks) {
        if (ks == KSTEPS - 1) asm volatile("cp.async.wait_group 0;" ::: "memory");
        else                  asm volatile("cp.async.wait_group 1;" ::: "memory");
        __syncthreads();

        const uint32_t sb = sbase + (ks & 1) * STAGE;

        #pragma unroll
        for (int kk = 0; kk < 4; ++kk) {             // 4 chunks of k32 (32 bytes)
            const uint32_t cb = (uint32_t)kk * 32;
            uint32_t ah[2][4], al[2][4], bh[2][4], bl[2][4];
            #pragma unroll
            for (int mf = 0; mf < 2; ++mf) {
                ldsm_x4(ah[mf][0], ah[mf][1], ah[mf][2], ah[mf][3],
                        sb + A_HI + SW128(a_row + mf * 16 * 128 + a_kb + cb));
                ldsm_x4(al[mf][0], al[mf][1], al[mf][2], al[mf][3],
                        sb + A_LO + SW128(a_row + mf * 16 * 128 + a_kb + cb));
            }
            #pragma unroll
            for (int np = 0; np < 2; ++np) {
                ldsm_x4(bh[np][0], bh[np][1], bh[np][2], bh[np][3],
                        sb + B_HI + SW128(b_row + np * 16 * 128 + b_kb + cb));
                ldsm_x4(bl[np][0], bl[np][1], bl[np][2], bl[np][3],
                        sb + B_LO + SW128(b_row + np * 16 * 128 + b_kb + cb));
            }
            #pragma unroll
            for (int mf = 0; mf < 2; ++mf)
                #pragma unroll
                for (int nf = 0; nf < 4; ++nf) {
                    const uint32_t* bhp = &bh[nf >> 1][(nf & 1) * 2];
                    const uint32_t* blp = &bl[nf >> 1][(nf & 1) * 2];
                    mma_s8(acc_hh[mf][nf], ah[mf], bhp);   // hi*hi
                    mma_s8(acc_x[mf][nf],  ah[mf], blp);   // hi*lo
                    mma_s8(acc_x[mf][nf],  al[mf], bhp);   // lo*hi
                }
        }
        __syncthreads();
        if (ks + 2 < KSTEPS) { load_stage(ks & 1, ks + 2); CPA_COMMIT(); }
    }

    // ---- epilogue: dequant + bias -> fp16 ----
    #pragma unroll
    for (int mf = 0; mf < 2; ++mf) {
        #pragma unroll
        for (int half_ = 0; half_ < 2; ++half_) {
            const int rg = m0 + wm * 32 + mf * 16 + grp + half_ * 8;
            __half* op = Out + (size_t)rg * NQKV + n0;
            #pragma unroll
            for (int nf = 0; nf < 4; ++nf) {
                const int cN = wn * 32 + nf * 8 + 2 * tig;
                const float v0 = (float)acc_hh[mf][nf][half_ * 2 + 0] * SCALE_HH
                               + (float)acc_x [mf][nf][half_ * 2 + 0] * SCALE_X
                               + bias[n0 + cN];
                const float v1 = (float)acc_hh[mf][nf][half_ * 2 + 1] * SCALE_HH
                               + (float)acc_x [mf][nf][half_ * 2 + 1] * SCALE_X
                               + bias[n0 + cN + 1];
                *reinterpret_cast<__half2*>(op + cN) = __floats2half2_rn(v0, v1);
            }
        }
    }
}

// ---------------- fp16 P-GEMM (R3-proven config, f32 accumulate) -----------
namespace gp {
constexpr int BM = 128, BN = 128, BK = 64;
constexpr int STAGE_A = BM * BK * 2;            // 16 KB
constexpr int STAGE_B = BN * BK * 2;            // 16 KB
constexpr int STAGE   = STAGE_A + STAGE_B;      // 32 KB
constexpr int NSTAGE  = 3;
constexpr int KSTEPS  = Cc / BK;                // 8
constexpr int DYN_SMEM = NSTAGE * STAGE;        // 96 KB
}

__global__ __launch_bounds__(256, 2) void gemm_p(
    const __half* __restrict__ A, const __half* __restrict__ Wt,
    const float* __restrict__ bias, float* __restrict__ Out)
{
    using namespace gp;
    extern __shared__ char smem[];
    const uint32_t sbase = smem_u32(smem);

    const int tid  = threadIdx.x;
    const int lane = tid & 31;
    const int warp = tid >> 5;
    const int wm   = warp & 3;       // 4 warps along M (32 rows)
    const int wn   = warp >> 2;      // 2 warps along N (64 cols)
    const int grp  = lane >> 2;
    const int tig  = lane & 3;
    const int n0   = blockIdx.x * BN;
    const int m0   = blockIdx.y * BM;

    const int ld_row = tid >> 1;
    const int ld_c0  = (tid & 1) * 4;
    const __half* gA = A  + (size_t)(m0 + ld_row) * Cc + ld_c0 * 8;
    const __half* gB = Wt + (size_t)(n0 + ld_row) * Cc + ld_c0 * 8;

    auto load_stage = [&](int slot, int ks) {
        const uint32_t sA = sbase + slot * STAGE;
        const uint32_t sB = sA + STAGE_A;
        const size_t koff = (size_t)ks * BK;
        #pragma unroll
        for (int i = 0; i < 4; ++i) {
            const uint32_t off = SW128(ld_row * 128 + (ld_c0 + i) * 16);
            cpa16(sA + off, gA + koff + i * 8);
            cpa16(sB + off, gB + koff + i * 8);
        }
    };

    const uint32_t a_row = (uint32_t)(wm * 32 + (lane & 15)) * 128;
    const uint32_t a_kb  = (uint32_t)(lane >> 4) * 16;
    const uint32_t b_row = (uint32_t)(wn * 64 + (lane & 7) + ((lane >> 4) << 3)) * 128;
    const uint32_t b_kb  = (uint32_t)((lane >> 3) & 1) * 16;

    float acc[2][8][4];
    #pragma unroll
    for (int mf = 0; mf < 2; ++mf)
        #pragma unroll
        for (int nf = 0; nf < 8; ++nf)
            #pragma unroll
            for (int t = 0; t < 4; ++t) acc[mf][nf][t] = 0.f;

    load_stage(0, 0); CPA_COMMIT();
    load_stage(1, 1); CPA_COMMIT();

    for (int ks = 0; ks < KSTEPS; ++ks) {
        if (ks == KSTEPS - 1) asm volatile("cp.async.wait_group 0;" ::: "memory");
        else                  asm volatile("cp.async.wait_group 1;" ::: "memory");
        __syncthreads();

        const uint32_t sA = sbase + (ks % NSTAGE) * STAGE;
        const uint32_t sB = sA + STAGE_A;

        #pragma unroll
        for (int kk = 0; kk < BK; kk += 16) {
            uint32_t a[2][4], b[4][4];
            #pragma unroll
            for (int mf = 0; mf < 2; ++mf)
                ldsm_x4(a[mf][0], a[mf][1], a[mf][2], a[mf][3],
                        sA + SW128(a_row + mf * 16 * 128 + a_kb + kk * 2));
            #pragma unroll
            for (int np = 0; np < 4; ++np)
                ldsm_x4(b[np][0], b[np][1], b[np][2], b[np][3],
                        sB + SW128(b_row + np * 16 * 128 + b_kb + kk * 2));
            #pragma unroll
            for (int mf = 0; mf < 2; ++mf)
                #pragma unroll
                for (int nf = 0; nf < 8; ++nf)
                    mma_fp16(acc[mf][nf], a[mf], &b[nf >> 1][(nf & 1) * 2]);
        }
        __syncthreads();
        if (ks + 2 < KSTEPS) { load_stage((ks + 2) % NSTAGE, ks + 2); CPA_COMMIT(); }
    }

    // epilogue: + bias, output roll
    #pragma unroll
    for (int mf = 0; mf < 2; ++mf) {
        #pragma unroll
        for (int half_ = 0; half_ < 2; ++half_) {
            const int rg = m0 + wm * 32 + mf * 16 + grp + half_ * 8;
            const int pos = rg & (Lc - 1);
            const size_t drow = (size_t)(rg & ~(Lc - 1)) + ((pos + Sc / 2) & (Lc - 1));
            float* op = Out + drow * Cc + n0;
            #pragma unroll
            for (int nf = 0; nf < 8; ++nf) {
                const int cN = wn * 64 + nf * 8 + 2 * tig;
                float2 o;
                o.x = acc[mf][nf][half_ * 2 + 0] + bias[n0 + cN];
                o.y = acc[mf][nf][half_ * 2 + 1] + bias[n0 + cN + 1];
                *reinterpret_cast<float2*>(op + cN) = o;
            }
        }
    }
}

// ---------------- windowed attention ---------------------------------------
__global__ __launch_bounds__(128) void attn_kernel(
    const __half* __restrict__ qkv, const float* __restrict__ bt,
    __half* __restrict__ att)
{
    __shared__ float sq  [4][Sc * 64];
    __shared__ float sk  [4][Sc * 68];
    __shared__ float sv  [4][Sc * 64];
    __shared__ float satt[4][64];

    const int lane = threadIdx.x & 31;
    const int wid  = threadIdx.x >> 5;
    const int w    = blockIdx.x >> 1;
    const int h    = ((blockIdx.x & 1) << 2) | wid;

    const size_t rowb = (size_t)w * Sc * NQKV + h * 64;

    #pragma unroll
    for (int p = 0; p < 2; ++p) {
        const int c  = p * 32 + lane;
        const int i  = c >> 3;
        const int d8 = (c & 7) * 8;
        const __half* g = qkv + rowb + (size_t)i * NQKV + d8;
        uint4 uq = *reinterpret_cast<const uint4*>(g);
        uint4 uk = *reinterpret_cast<const uint4*>(g + Cc);
        uint4 uv = *reinterpret_cast<const uint4*>(g + 2 * Cc);
        const __half2* hq = reinterpret_cast<const __half2*>(&uq);
        const __half2* hk = reinterpret_cast<const __half2*>(&uk);
        const __half2* hv = reinterpret_cast<const __half2*>(&uv);
        #pragma unroll
        for (int j = 0; j < 4; ++j) {
            const float2 fq = __half22float2(hq[j]);
            const float2 fk = __half22float2(hk[j]);
            const float2 fv = __half22float2(hv[j]);
            sq[wid][i * 64 + d8 + 2 * j]     = fq.x;
            sq[wid][i * 64 + d8 + 2 * j + 1] = fq.y;
            sk[wid][i * 68 + d8 + 2 * j]     = fk.x;
            sk[wid][i * 68 + d8 + 2 * j + 1] = fk.y;
            sv[wid][i * 64 + d8 + 2 * j]     = fv.x;
            sv[wid][i * 64 + d8 + 2 * j + 1] = fv.y;
        }
    }
    __syncwarp();

    const int i0 = lane >> 3;
    const int j  = lane & 7;
    float e0 = 0.f, e1 = 0.f;
    const float* qr0 = &sq[wid][i0 * 64];
    const float* qr1 = &sq[wid][(i0 + 4) * 64];
    const float* kr  = &sk[wid][j * 68];
    #pragma unroll
    for (int d = 0; d < 64; ++d) {
        const float kv = kr[d];
        e0 = fmaf(qr0[d], kv, e0);
        e1 = fmaf(qr1[d], kv, e1);
    }
    const float scale = 0.044194173824159216f;   // 1/sqrt(512)
    e0 = e0 * scale + bt[(j - i0 + 7) * Hc + h];
    e1 = e1 * scale + bt[(j - i0 + 3) * Hc + h];

    if ((w & (NWc - 1)) == NWc - 1) {
        if (j >= 4) e0 -= 100.f;
        else        e1 -= 100.f;
    }

    float m0 = e0, m1 = e1;
    #pragma unroll
    for (int off = 4; off > 0; off >>= 1) {
        m0 = fmaxf(m0, __shfl_xor_sync(0xffffffffu, m0, off));
        m1 = fmaxf(m1, __shfl_xor_sync(0xffffffffu, m1, off));
    }
    float p0 = __expf(e0 - m0), p1 = __expf(e1 - m1);
    float s0 = p0, s1 = p1;
    #pragma unroll
    for (int off = 4; off > 0; off >>= 1) {
        s0 += __shfl_xor_sync(0xffffffffu, s0, off);
        s1 += __shfl_xor_sync(0xffffffffu, s1, off);
    }
    satt[wid][i0 * 8 + j]       = p0 / s0;
    satt[wid][(i0 + 4) * 8 + j] = p1 / s1;
    __syncwarp();

    const size_t ob = (size_t)w * Sc * Cc + h * 64;
    #pragma unroll
    for (int i = 0; i < 8; ++i) {
        float a0 = 0.f, a1 = 0.f;
        #pragma unroll
        for (int t = 0; t < 8; ++t) {
            const float a = satt[wid][i * 8 + t];
            a0 = fmaf(a, sv[wid][t * 64 + lane],      a0);
            a1 = fmaf(a, sv[wid][t * 64 + lane + 32], a1);
        }
        att[ob + (size_t)i * Cc + lane]      = __float2half(a0);
        att[ob + (size_t)i * Cc + lane + 32] = __float2half(a1);
    }
}

// ---------------- launch -----------------------------------------------------
extern "C" void kernel_launch(void* const* d_in, const int* in_sizes, int n_in,
                              void* d_out, int out_size)
{
    const float* x  = (const float*)d_in[0];
    const float* Wq = (const float*)d_in[1];
    const float* bq = (const float*)d_in[2];
    const float* Wk = (const float*)d_in[3];
    const float* bk = (const float*)d_in[4];
    const float* Wv = (const float*)d_in[5];
    const float* bv = (const float*)d_in[6];
    const float* Wp = (const float*)d_in[7];
    const float* bp = (const float*)d_in[8];
    const float* bt = (const float*)d_in[9];
    float* out = (float*)d_out;

    signed char *px8h, *px8l, *pw8h, *pw8l;
    __half *pqkv, *patt, *pwpt;
    float* pbqkv;
    cudaGetSymbolAddress((void**)&px8h, g_x8h);
    cudaGetSymbolAddress((void**)&px8l, g_x8l);
    cudaGetSymbolAddress((void**)&pw8h, g_w8h);
    cudaGetSymbolAddress((void**)&pw8l, g_w8l);
    cudaGetSymbolAddress((void**)&pqkv, g_qkv);
    cudaGetSymbolAddress((void**)&patt, g_att);
    cudaGetSymbolAddress((void**)&pwpt, g_wpt);
    cudaGetSymbolAddress((void**)&pbqkv, g_bqkv);

    cudaFuncSetAttribute((const void*)gemm_s8qkv,
                         cudaFuncAttributeMaxDynamicSharedMemorySize, gs::DYN_SMEM);
    cudaFuncSetAttribute((const void*)gemm_p,
                         cudaFuncAttributeMaxDynamicSharedMemorySize, gp::DYN_SMEM);

    WArgs wa;
    wa.src[0] = Wq; wa.src[1] = Wk; wa.src[2] = Wv; wa.src[3] = Wp;
    wa.w8h = pw8h; wa.w8l = pw8l; wa.wpt = pwpt;
    prep_w_mixed<<<dim3(16, 16, 4), 256>>>(wa);
    concat_bias<<<6, 256>>>(bq, bk, bv, pbqkv);

    quant_x<<<(Mc * Cc / 8) / 256, 256>>>(x, px8h, px8l);

    // N-fastest grid: weight planes resident in L2, A tiles reused across N.
    dim3 g1(NQKV / gs::BN, Mc / gs::BM);   // (12, 1024)
    gemm_s8qkv<<<g1, 512, gs::DYN_SMEM>>>(px8h, px8l, pw8h, pw8l, pbqkv, pqkv);

    attn_kernel<<<Bc * NWc * 2, 128>>>(pqkv, bt, patt);

    dim3 g2(Cc / gp::BN, Mc / gp::BM);     // (4, 1024)
    gemm_p<<<g2, 256, gp::DYN_SMEM>>>(patt, pwpt, bp, out);
}

// round 13
// speedup vs baseline: 3.7647x; 3.7647x over previous
#include <cuda_runtime.h>
#include <cuda_fp16.h>
#include <cstdint>

namespace {
constexpr int Bc  = 32;
constexpr int Lc  = 4096;
constexpr int Cc  = 512;
constexpr int Hc  = 8;
constexpr int Sc  = 8;
constexpr int NWc = Lc / Sc;
constexpr int Mc  = Bc * Lc;           // 131072
constexpr int NQKV = 3 * Cc;           // 1536
}

// ---------------- scratch (__device__ globals; no allocations) -------------
__device__ __half g_x16 [(size_t)Mc * Cc];          // rolled x, fp16
__device__ __half g_qkv [(size_t)Mc * NQKV];        // fused q|k|v, fp16
__device__ __half g_att [(size_t)Mc * Cc];          // attention out, fp16
__device__ __half g_wt  [(size_t)NQKV * Cc];        // Wq|Wk|Wv transposed [n][k]
__device__ __half g_wpt [(size_t)Cc * Cc];          // Wp transposed
__device__ float  g_bqkv[NQKV];

// ---------------- helpers ---------------------------------------------------
__device__ __forceinline__ uint32_t smem_u32(const void* p) {
    uint32_t a;
    asm("{ .reg .u64 t; cvta.to.shared.u64 t, %1; cvt.u32.u64 %0, t; }" : "=r"(a) : "l"(p));
    return a;
}
#define SW128(off) ((off) ^ (((off) >> 3) & 0x70))

__device__ __forceinline__ void cpa16(uint32_t saddr, const void* g) {
    asm volatile("cp.async.cg.shared.global [%0], [%1], 16;" :: "r"(saddr), "l"(g) : "memory");
}
#define CPA_COMMIT() asm volatile("cp.async.commit_group;" ::: "memory")

__device__ __forceinline__ void ldsm_x4(uint32_t& r0, uint32_t& r1, uint32_t& r2, uint32_t& r3,
                                        uint32_t addr) {
    asm volatile("ldmatrix.sync.aligned.m8n8.x4.shared.b16 {%0,%1,%2,%3}, [%4];"
                 : "=r"(r0), "=r"(r1), "=r"(r2), "=r"(r3) : "r"(addr));
}
__device__ __forceinline__ void mma_fp16(float c[4], const uint32_t a[4], const uint32_t b[2]) {
    asm volatile(
        "mma.sync.aligned.m16n8k16.row.col.f32.f16.f16.f32 "
        "{%0,%1,%2,%3},{%4,%5,%6,%7},{%8,%9},{%0,%1,%2,%3};\n"
        : "+f"(c[0]), "+f"(c[1]), "+f"(c[2]), "+f"(c[3])
        : "r"(a[0]), "r"(a[1]), "r"(a[2]), "r"(a[3]), "r"(b[0]), "r"(b[1]));
}

// ---------------- prep kernels ----------------------------------------------
struct WPrepArgs {
    const float* src[4];
    __half* dst[4];
};

__global__ __launch_bounds__(256) void prep_w_all(WPrepArgs args)
{
    __shared__ float t[32][33];
    const float* W  = args.src[blockIdx.z];
    __half* Wt      = args.dst[blockIdx.z];
    const int tx = threadIdx.x & 31, ty = threadIdx.x >> 5;
    const int bn = blockIdx.x * 32, bk = blockIdx.y * 32;
    #pragma unroll
    for (int i = 0; i < 32; i += 8)
        t[ty + i][tx] = W[(size_t)(bk + ty + i) * Cc + bn + tx];
    __syncthreads();
    #pragma unroll
    for (int i = 0; i < 32; i += 8)
        Wt[(size_t)(bn + ty + i) * Cc + bk + tx] = __float2half(t[tx][ty + i]);
}

__global__ void concat_bias(const float* __restrict__ b0, const float* __restrict__ b1,
                            const float* __restrict__ b2, float* __restrict__ dst)
{
    const int i = blockIdx.x * 256 + threadIdx.x;
    if (i < NQKV) {
        const float* s = (i < Cc) ? b0 : (i < 2 * Cc) ? b1 : b2;
        dst[i] = s[i & (Cc - 1)];
    }
}

__global__ __launch_bounds__(256) void convert_x(
    const float* __restrict__ x, __half* __restrict__ xo)
{
    const size_t idx = (size_t)blockIdx.x * 256 + threadIdx.x;  // 8-elt chunk id
    const int row = (int)(idx >> 6);
    const int c8  = (int)(idx & 63) * 8;
    const int pos = row & (Lc - 1);
    const size_t srow = (size_t)(row & ~(Lc - 1)) + ((pos + Sc / 2) & (Lc - 1));
    const float4* src = reinterpret_cast<const float4*>(x + srow * Cc + c8);
    const float4 v0 = src[0], v1 = src[1];
    __half2 o[4];
    o[0] = __floats2half2_rn(v0.x, v0.y);
    o[1] = __floats2half2_rn(v0.z, v0.w);
    o[2] = __floats2half2_rn(v1.x, v1.y);
    o[3] = __floats2half2_rn(v1.z, v1.w);
    *reinterpret_cast<uint4*>(xo + idx * 8) = *reinterpret_cast<uint4*>(o);
}

// ---------------- HMMA GEMM (R3 config + single-barrier mainloop) ----------
// Out[M, Ntot] = A[M,512](fp16) @ Wt[Ntot,512]^T + bias.
// CTA 128x128x64, 8 warps (4M x 2N), warp tile 32x64, 3-stage cp.async,
// ONE barrier per K-step, 2 CTAs/SM, f32 accumulate (the saturated config).
namespace gh {
constexpr int BM = 128, BN = 128, BK = 64;
constexpr int STAGE_A = BM * BK * 2;            // 16 KB
constexpr int STAGE_B = BN * BK * 2;            // 16 KB
constexpr int STAGE   = STAGE_A + STAGE_B;      // 32 KB
constexpr int NSTAGE  = 3;
constexpr int KSTEPS  = Cc / BK;                // 8
constexpr int DYN_SMEM = NSTAGE * STAGE;        // 96 KB
}

template <typename OutT, bool ROLL_OUT>
__global__ __launch_bounds__(256, 2) void gemm_hmma(
    const __half* __restrict__ A, const __half* __restrict__ Wt,
    const float* __restrict__ bias, OutT* __restrict__ Out, int ldn)
{
    using namespace gh;
    extern __shared__ char smem[];
    const uint32_t sbase = smem_u32(smem);

    const int tid  = threadIdx.x;
    const int lane = tid & 31;
    const int warp = tid >> 5;
    const int wm   = warp & 3;       // 4 warps along M (32 rows each)
    const int wn   = warp >> 2;      // 2 warps along N (64 cols each)
    const int grp  = lane >> 2;
    const int tig  = lane & 3;
    const int n0   = blockIdx.x * BN;           // N fastest -> L2-friendly
    const int m0   = blockIdx.y * BM;

    // cp.async geometry: 2 threads per 128B row, 4 chunks each
    const int ld_row = tid >> 1;               // 0..127
    const int ld_c0  = (tid & 1) * 4;          // chunk 0..3 / 4..7
    const __half* gA = A  + (size_t)(m0 + ld_row) * Cc + ld_c0 * 8;
    const __half* gB = Wt + (size_t)(n0 + ld_row) * Cc + ld_c0 * 8;

    auto load_stage = [&](int slot, int ks) {
        const uint32_t sA = sbase + slot * STAGE;
        const uint32_t sB = sA + STAGE_A;
        const size_t koff = (size_t)ks * BK;
        #pragma unroll
        for (int i = 0; i < 4; ++i) {
            const uint32_t off = SW128(ld_row * 128 + (ld_c0 + i) * 16);
            cpa16(sA + off, gA + koff + i * 8);
            cpa16(sB + off, gB + koff + i * 8);
        }
    };

    // ldmatrix per-lane address components
    const uint32_t a_row = (uint32_t)(wm * 32 + (lane & 15)) * 128;
    const uint32_t a_kb  = (uint32_t)(lane >> 4) * 16;
    const uint32_t b_row = (uint32_t)(wn * 64 + (lane & 7) + ((lane >> 4) << 3)) * 128;
    const uint32_t b_kb  = (uint32_t)((lane >> 3) & 1) * 16;

    float acc[2][8][4];
    #pragma unroll
    for (int mf = 0; mf < 2; ++mf)
        #pragma unroll
        for (int nf = 0; nf < 8; ++nf)
            #pragma unroll
            for (int t = 0; t < 4; ++t) acc[mf][nf][t] = 0.f;

    load_stage(0, 0); CPA_COMMIT();
    load_stage(1, 1); CPA_COMMIT();

    for (int ks = 0; ks < KSTEPS; ++ks) {
        if (ks == KSTEPS - 1) asm volatile("cp.async.wait_group 0;" ::: "memory");
        else                  asm volatile("cp.async.wait_group 1;" ::: "memory");
        __syncthreads();   // stage ks resident AND stage ks-1 fully consumed

        // refill the slot just freed by stage ks-1 (single-barrier pattern)
        if (ks + 2 < KSTEPS) { load_stage((ks + 2) % NSTAGE, ks + 2); CPA_COMMIT(); }

        const uint32_t sA = sbase + (ks % NSTAGE) * STAGE;
        const uint32_t sB = sA + STAGE_A;

        #pragma unroll
        for (int kk = 0; kk < BK; kk += 16) {
            uint32_t a[2][4], b[4][4];
            #pragma unroll
            for (int mf = 0; mf < 2; ++mf)
                ldsm_x4(a[mf][0], a[mf][1], a[mf][2], a[mf][3],
                        sA + SW128(a_row + mf * 16 * 128 + a_kb + kk * 2));
            #pragma unroll
            for (int np = 0; np < 4; ++np)
                ldsm_x4(b[np][0], b[np][1], b[np][2], b[np][3],
                        sB + SW128(b_row + np * 16 * 128 + b_kb + kk * 2));
            #pragma unroll
            for (int mf = 0; mf < 2; ++mf)
                #pragma unroll
                for (int nf = 0; nf < 8; ++nf)
                    mma_fp16(acc[mf][nf], a[mf], &b[nf >> 1][(nf & 1) * 2]);
        }
    }

    // ---- epilogue: + bias ----
    #pragma unroll
    for (int mf = 0; mf < 2; ++mf) {
        #pragma unroll
        for (int half_ = 0; half_ < 2; ++half_) {
            const int rg = m0 + wm * 32 + mf * 16 + grp + half_ * 8;
            size_t drow;
            if (ROLL_OUT) {
                const int pos = rg & (Lc - 1);
                drow = (size_t)(rg & ~(Lc - 1)) + ((pos + Sc / 2) & (Lc - 1));
            } else {
                drow = (size_t)rg;
            }
            OutT* op = Out + drow * (size_t)ldn + n0;
            #pragma unroll
            for (int nf = 0; nf < 8; ++nf) {
                const int cN = wn * 64 + nf * 8 + 2 * tig;
                const float v0 = acc[mf][nf][half_ * 2 + 0] + bias[n0 + cN];
                const float v1 = acc[mf][nf][half_ * 2 + 1] + bias[n0 + cN + 1];
                if constexpr (sizeof(OutT) == 2) {
                    *reinterpret_cast<__half2*>(op + cN) = __floats2half2_rn(v0, v1);
                } else {
                    float2 o; o.x = v0; o.y = v1;
                    *reinterpret_cast<float2*>(op + cN) = o;
                }
            }
        }
    }
}

// ---------------- windowed attention ---------------------------------------
__global__ __launch_bounds__(128) void attn_kernel(
    const __half* __restrict__ qkv, const float* __restrict__ bt,
    __half* __restrict__ att)
{
    __shared__ float sq  [4][Sc * 64];
    __shared__ float sk  [4][Sc * 68];
    __shared__ float sv  [4][Sc * 64];
    __shared__ float satt[4][64];

    const int lane = threadIdx.x & 31;
    const int wid  = threadIdx.x >> 5;
    const int w    = blockIdx.x >> 1;
    const int h    = ((blockIdx.x & 1) << 2) | wid;

    const size_t rowb = (size_t)w * Sc * NQKV + h * 64;

    #pragma unroll
    for (int p = 0; p < 2; ++p) {
        const int c  = p * 32 + lane;       // 0..63
        const int i  = c >> 3;
        const int d8 = (c & 7) * 8;
        const __half* g = qkv + rowb + (size_t)i * NQKV + d8;
        uint4 uq = *reinterpret_cast<const uint4*>(g);
        uint4 uk = *reinterpret_cast<const uint4*>(g + Cc);
        uint4 uv = *reinterpret_cast<const uint4*>(g + 2 * Cc);
        const __half2* hq = reinterpret_cast<const __half2*>(&uq);
        const __half2* hk = reinterpret_cast<const __half2*>(&uk);
        const __half2* hv = reinterpret_cast<const __half2*>(&uv);
        #pragma unroll
        for (int j = 0; j < 4; ++j) {
            const float2 fq = __half22float2(hq[j]);
            const float2 fk = __half22float2(hk[j]);
            const float2 fv = __half22float2(hv[j]);
            sq[wid][i * 64 + d8 + 2 * j]     = fq.x;
            sq[wid][i * 64 + d8 + 2 * j + 1] = fq.y;
            sk[wid][i * 68 + d8 + 2 * j]     = fk.x;
            sk[wid][i * 68 + d8 + 2 * j + 1] = fk.y;
            sv[wid][i * 64 + d8 + 2 * j]     = fv.x;
            sv[wid][i * 64 + d8 + 2 * j + 1] = fv.y;
        }
    }
    __syncwarp();

    const int i0 = lane >> 3;
    const int j  = lane & 7;
    float e0 = 0.f, e1 = 0.f;
    const float* qr0 = &sq[wid][i0 * 64];
    const float* qr1 = &sq[wid][(i0 + 4) * 64];
    const float* kr  = &sk[wid][j * 68];
    #pragma unroll
    for (int d = 0; d < 64; ++d) {
        const float kv = kr[d];
        e0 = fmaf(qr0[d], kv, e0);
        e1 = fmaf(qr1[d], kv, e1);
    }
    const float scale = 0.044194173824159216f;   // 1/sqrt(512)
    e0 = e0 * scale + bt[(j - i0 + 7) * Hc + h];
    e1 = e1 * scale + bt[(j - i0 + 3) * Hc + h];

    if ((w & (NWc - 1)) == NWc - 1) {
        if (j >= 4) e0 -= 100.f;
        else        e1 -= 100.f;
    }

    float m0 = e0, m1 = e1;
    #pragma unroll
    for (int off = 4; off > 0; off >>= 1) {
        m0 = fmaxf(m0, __shfl_xor_sync(0xffffffffu, m0, off));
        m1 = fmaxf(m1, __shfl_xor_sync(0xffffffffu, m1, off));
    }
    float p0 = __expf(e0 - m0), p1 = __expf(e1 - m1);
    float s0 = p0, s1 = p1;
    #pragma unroll
    for (int off = 4; off > 0; off >>= 1) {
        s0 += __shfl_xor_sync(0xffffffffu, s0, off);
        s1 += __shfl_xor_sync(0xffffffffu, s1, off);
    }
    satt[wid][i0 * 8 + j]       = p0 / s0;
    satt[wid][(i0 + 4) * 8 + j] = p1 / s1;
    __syncwarp();

    const size_t ob = (size_t)w * Sc * Cc + h * 64;
    #pragma unroll
    for (int i = 0; i < 8; ++i) {
        float a0 = 0.f, a1 = 0.f;
        #pragma unroll
        for (int t = 0; t < 8; ++t) {
            const float a = satt[wid][i * 8 + t];
            a0 = fmaf(a, sv[wid][t * 64 + lane],      a0);
            a1 = fmaf(a, sv[wid][t * 64 + lane + 32], a1);
        }
        att[ob + (size_t)i * Cc + lane]      = __float2half(a0);
        att[ob + (size_t)i * Cc + lane + 32] = __float2half(a1);
    }
}

// ---------------- launch -----------------------------------------------------
extern "C" void kernel_launch(void* const* d_in, const int* in_sizes, int n_in,
                              void* d_out, int out_size)
{
    const float* x  = (const float*)d_in[0];
    const float* Wq = (const float*)d_in[1];
    const float* bq = (const float*)d_in[2];
    const float* Wk = (const float*)d_in[3];
    const float* bk = (const float*)d_in[4];
    const float* Wv = (const float*)d_in[5];
    const float* bv = (const float*)d_in[6];
    const float* Wp = (const float*)d_in[7];
    const float* bp = (const float*)d_in[8];
    const float* bt = (const float*)d_in[9];
    float* out = (float*)d_out;

    __half *px16, *pqkv, *patt, *pwt, *pwpt;
    float* pbqkv;
    cudaGetSymbolAddress((void**)&px16, g_x16);
    cudaGetSymbolAddress((void**)&pqkv, g_qkv);
    cudaGetSymbolAddress((void**)&patt, g_att);
    cudaGetSymbolAddress((void**)&pwt,  g_wt);
    cudaGetSymbolAddress((void**)&pwpt, g_wpt);
    cudaGetSymbolAddress((void**)&pbqkv, g_bqkv);

    cudaFuncSetAttribute(gemm_hmma<__half, false>,
                         cudaFuncAttributeMaxDynamicSharedMemorySize, gh::DYN_SMEM);
    cudaFuncSetAttribute(gemm_hmma<float, true>,
                         cudaFuncAttributeMaxDynamicSharedMemorySize, gh::DYN_SMEM);

    WPrepArgs wa;
    wa.src[0] = Wq; wa.src[1] = Wk; wa.src[2] = Wv; wa.src[3] = Wp;
    wa.dst[0] = pwt;
    wa.dst[1] = pwt + (size_t)Cc * Cc;
    wa.dst[2] = pwt + (size_t)2 * Cc * Cc;
    wa.dst[3] = pwpt;
    prep_w_all<<<dim3(16, 16, 4), 256>>>(wa);
    concat_bias<<<6, 256>>>(bq, bk, bv, pbqkv);

    convert_x<<<(Mc * Cc / 8) / 256, 256>>>(x, px16);

    dim3 g1(NQKV / gh::BN, Mc / gh::BM);   // (12, 1024), N-fastest
    gemm_hmma<__half, false><<<g1, 256, gh::DYN_SMEM>>>(px16, pwt, pbqkv, pqkv, NQKV);

    attn_kernel<<<Bc * NWc * 2, 128>>>(pqkv, bt, patt);

    dim3 g2(Cc / gh::BN, Mc / gh::BM);     // (4, 1024)
    gemm_hmma<float, true><<<g2, 256, gh::DYN_SMEM>>>(patt, pwpt, bp, out, Cc);
}